// round 5
// baseline (speedup 1.0000x reference)
#include <cuda_runtime.h>
#include <cuda_bf16.h>
#include <stdint.h>

#define NNODES 100000
#define NEDGES 1600000
#define FDIM   64
#define NCLS   2
#define SCAN_T 1024
#define CHUNK  ((NNODES + SCAN_T - 1) / SCAN_T)   // 98

// Scratch (__device__ globals; no allocations allowed)
__device__ int   g_deg[NNODES];
__device__ int   g_cursor[NNODES];
__device__ int   g_rowstart[NNODES + 1];
__device__ int   g_col[NEDGES];          // CSR column (source node) per slot
__device__ float g_dinv[NNODES];
__device__ float g_h[NNODES * FDIM];     // x @ W1
__device__ float g_h2[NNODES * NCLS];    // relu(agg1 + b1) @ W2

__device__ __forceinline__ int clampi(int v) {
    return min(max(v, 0), NNODES - 1);
}

// ---------------------------------------------------------------------------
// K1: zero degree + cursor
__global__ void k_zero(void) {
    int i = blockIdx.x * blockDim.x + threadIdx.x;
    if (i < NNODES) { g_deg[i] = 0; g_cursor[i] = 0; }
}

// K2: integer degree histogram over edge targets (row = edge_index[0])
__global__ void k_degree(const int* __restrict__ ei) {
    int e = blockIdx.x * blockDim.x + threadIdx.x;
    if (e >= NEDGES) return;
    atomicAdd(&g_deg[clampi(ei[e])], 1);
}

// K3: single-block exclusive scan of g_deg -> g_rowstart; also dinv.
__global__ void k_scan(void) {
    __shared__ int sp[SCAN_T];
    const int t = threadIdx.x;
    const int lo = min(t * CHUNK, NNODES);
    const int hi = min(lo + CHUNK, NNODES);
    int mysum = 0;
    for (int i = lo; i < hi; i++) mysum += g_deg[i];
    sp[t] = mysum;
    __syncthreads();
    // Hillis-Steele inclusive scan over 1024 partials
    for (int off = 1; off < SCAN_T; off <<= 1) {
        int v = 0;
        if (t >= off) v = sp[t - off];
        __syncthreads();
        sp[t] += v;
        __syncthreads();
    }
    int run = sp[t] - mysum;   // exclusive prefix for this chunk
    for (int i = lo; i < hi; i++) {
        g_rowstart[i] = run;
        run += g_deg[i];
        g_dinv[i] = rsqrtf((float)g_deg[i] + 1.0f);   // +1 = self loop
    }
    if (t == SCAN_T - 1) g_rowstart[NNODES] = sp[SCAN_T - 1];
}

// K4: fill CSR columns
__global__ void k_fill(const int* __restrict__ ei) {
    int e = blockIdx.x * blockDim.x + threadIdx.x;
    if (e >= NEDGES) return;
    int r = clampi(ei[e]);
    int c = clampi(ei[NEDGES + e]);
    int slot = g_rowstart[r] + atomicAdd(&g_cursor[r], 1);
    g_col[slot] = c;
}

// K5: h = x @ W1.  8 warps/block, warp handles 8 nodes, W1 in shared.
__global__ void k_gemm1(const float* __restrict__ x, const float* __restrict__ W1) {
    __shared__ float Ws[FDIM * FDIM];
    __shared__ float xs[8][FDIM];
    for (int i = threadIdx.x; i < FDIM * FDIM; i += blockDim.x) Ws[i] = W1[i];
    __syncthreads();
    const int warp = threadIdx.x >> 5;
    const int lane = threadIdx.x & 31;
    const int base = (blockIdx.x * 8 + warp) * 8;
    #pragma unroll 1
    for (int j = 0; j < 8; j++) {
        int n = base + j;
        if (n >= NNODES) break;
        float2 xv = *(const float2*)&x[(size_t)n * FDIM + lane * 2];
        xs[warp][lane * 2]     = xv.x;
        xs[warp][lane * 2 + 1] = xv.y;
        __syncwarp();
        float a0 = 0.0f, a1 = 0.0f;
        #pragma unroll
        for (int k = 0; k < FDIM; k++) {
            float xk = xs[warp][k];
            a0 = fmaf(xk, Ws[k * FDIM + lane], a0);
            a1 = fmaf(xk, Ws[k * FDIM + lane + 32], a1);
        }
        g_h[n * FDIM + lane]      = a0;
        g_h[n * FDIM + lane + 32] = a1;
        __syncwarp();
    }
}

// K6: fused layer-1 aggregation (gather) + bias + ReLU + GEMM2 -> g_h2.
// One block of 64 threads per node; thread t owns feature t.
__global__ void k_fused1(const float* __restrict__ b1, const float* __restrict__ W2) {
    const int n = blockIdx.x;
    const int t = threadIdx.x;
    __shared__ float s0[2], s1[2];

    const float din = g_dinv[n];
    const int start = g_rowstart[n];
    const int end   = g_rowstart[n + 1];

    // self loop
    float acc = (din * din) * g_h[n * FDIM + t];
    // gather incoming edges (coalesced 256B row reads from L2-resident g_h)
    for (int s = start; s < end; s++) {
        int c = g_col[s];
        float w = din * g_dinv[c];
        acc = fmaf(w, g_h[c * FDIM + t], acc);
    }
    float v = fmaxf(acc + b1[t], 0.0f);

    // GEMM2: logits[n] = v @ W2 (64x2), block reduction over 64 threads
    float c0 = v * W2[t * 2];
    float c1 = v * W2[t * 2 + 1];
    #pragma unroll
    for (int off = 16; off > 0; off >>= 1) {
        c0 += __shfl_down_sync(0xFFFFFFFFu, c0, off);
        c1 += __shfl_down_sync(0xFFFFFFFFu, c1, off);
    }
    const int warp = t >> 5;
    if ((t & 31) == 0) { s0[warp] = c0; s1[warp] = c1; }
    __syncthreads();
    if (t == 0) {
        g_h2[n * 2]     = s0[0] + s0[1];
        g_h2[n * 2 + 1] = s1[0] + s1[1];
    }
}

// K7: fused layer-2 aggregation (gather) + bias + softmax -> out.
// Warp per node; lanes stride over incoming edges.
__global__ void k_fused2(const float* __restrict__ b2, float* __restrict__ out) {
    const int lane = threadIdx.x & 31;
    const int n = (blockIdx.x * blockDim.x + threadIdx.x) >> 5;
    if (n >= NNODES) return;
    const float din = g_dinv[n];
    const int start = g_rowstart[n];
    const int end   = g_rowstart[n + 1];
    float a0 = 0.0f, a1 = 0.0f;
    for (int s = start + lane; s < end; s += 32) {
        int c = g_col[s];
        float w = din * g_dinv[c];
        a0 = fmaf(w, g_h2[c * 2],     a0);
        a1 = fmaf(w, g_h2[c * 2 + 1], a1);
    }
    #pragma unroll
    for (int off = 16; off > 0; off >>= 1) {
        a0 += __shfl_down_sync(0xFFFFFFFFu, a0, off);
        a1 += __shfl_down_sync(0xFFFFFFFFu, a1, off);
    }
    if (lane == 0) {
        float sl = din * din;
        float l0 = b2[0] + fmaf(sl, g_h2[n * 2],     a0);
        float l1 = b2[1] + fmaf(sl, g_h2[n * 2 + 1], a1);
        float m = fmaxf(l0, l1);
        float e0 = __expf(l0 - m), e1 = __expf(l1 - m);
        float inv = 1.0f / (e0 + e1);
        out[n * 2]     = e0 * inv;
        out[n * 2 + 1] = e1 * inv;
    }
}

extern "C" void kernel_launch(void* const* d_in, const int* in_sizes, int n_in,
                              void* d_out, int out_size) {
    const float* x  = (const float*)d_in[0];
    const int*   ei = (const int*)d_in[1];     // int32 (JAX x64 disabled)
    const float* W1 = (const float*)d_in[2];
    const float* b1 = (const float*)d_in[3];
    const float* W2 = (const float*)d_in[4];
    const float* b2 = (const float*)d_in[5];
    float* out = (float*)d_out;

    const int T = 256;
    k_zero   <<<(NNODES + T - 1) / T, T>>>();
    k_degree <<<(NEDGES + T - 1) / T, T>>>(ei);
    k_scan   <<<1, SCAN_T>>>();
    k_fill   <<<(NEDGES + T - 1) / T, T>>>(ei);
    k_gemm1  <<<(NNODES + 63) / 64, T>>>(x, W1);
    k_fused1 <<<NNODES, FDIM>>>(b1, W2);
    k_fused2 <<<(NNODES * 32 + T - 1) / T, T>>>(b2, out);
}

// round 6
// speedup vs baseline: 2.1580x; 2.1580x over previous
#include <cuda_runtime.h>
#include <cuda_bf16.h>
#include <stdint.h>

#define NNODES 100000
#define NEDGES 1600000
#define FDIM   64
#define NCLS   2
#define NB     98            // ceil(NNODES/1024)

// Scratch (__device__ globals; no allocations allowed)
__device__ int   g_deg[NNODES];
__device__ int   g_cursor[NNODES];
__device__ int   g_rowstart[NNODES + 1];
__device__ int2  g_cw[NEDGES];           // per CSR slot: {col, bits(dinv[col])}
__device__ float g_dinv[NNODES];
__device__ float g_h[NNODES * FDIM];     // x @ W1
__device__ float g_h2[NNODES * NCLS];    // relu(agg1 + b1) @ W2
__device__ int   g_partial[NB];
__device__ int   g_blockoff[NB];

__device__ __forceinline__ int clampi(int v) {
    return min(max(v, 0), NNODES - 1);
}

// ---------------------------------------------------------------------------
// K1: zero degree + cursor
__global__ void k_zero(void) {
    int i = blockIdx.x * blockDim.x + threadIdx.x;
    if (i < NNODES) { g_deg[i] = 0; g_cursor[i] = 0; }
}

// K2: degree histogram over edge targets, 4 edges/thread via int4
__global__ void k_degree(const int* __restrict__ ei) {
    int i = blockIdx.x * blockDim.x + threadIdx.x;
    if (i >= NEDGES / 4) return;
    int4 v = ((const int4*)ei)[i];
    atomicAdd(&g_deg[clampi(v.x)], 1);
    atomicAdd(&g_deg[clampi(v.y)], 1);
    atomicAdd(&g_deg[clampi(v.z)], 1);
    atomicAdd(&g_deg[clampi(v.w)], 1);
}

// K3a: per-1024-chunk partial sums
__global__ void k_scan_a(void) {
    __shared__ int ws[8];
    const int t = threadIdx.x;
    const int base = blockIdx.x * 1024;
    int sum = 0;
    #pragma unroll
    for (int i = 0; i < 4; i++) {
        int idx = base + t + i * 256;
        if (idx < NNODES) sum += g_deg[idx];
    }
    #pragma unroll
    for (int off = 16; off > 0; off >>= 1) sum += __shfl_down_sync(~0u, sum, off);
    if ((t & 31) == 0) ws[t >> 5] = sum;
    __syncthreads();
    if (t == 0) {
        int s = 0;
        #pragma unroll
        for (int w = 0; w < 8; w++) s += ws[w];
        g_partial[blockIdx.x] = s;
    }
}

// K3b: scan the 98 partials (one block)
__global__ void k_scan_b(void) {
    __shared__ int sp[128];
    const int t = threadIdx.x;
    int v = (t < NB) ? g_partial[t] : 0;
    sp[t] = v;
    __syncthreads();
    for (int off = 1; off < 128; off <<= 1) {
        int u = (t >= off) ? sp[t - off] : 0;
        __syncthreads();
        sp[t] += u;
        __syncthreads();
    }
    if (t < NB) g_blockoff[t] = sp[t] - v;   // exclusive
}

// K3c: intra-chunk exclusive scan + write rowstart & dinv
__global__ void k_scan_c(void) {
    __shared__ int wsum[32];
    const int t = threadIdx.x;
    const int lane = t & 31, wid = t >> 5;
    const int i = blockIdx.x * 1024 + t;
    int d = (i < NNODES) ? g_deg[i] : 0;
    int incl = d;
    #pragma unroll
    for (int off = 1; off < 32; off <<= 1) {
        int v = __shfl_up_sync(~0u, incl, off);
        if (lane >= off) incl += v;
    }
    if (lane == 31) wsum[wid] = incl;
    __syncthreads();
    if (wid == 0) {
        int v = wsum[lane];
        #pragma unroll
        for (int off = 1; off < 32; off <<= 1) {
            int u = __shfl_up_sync(~0u, v, off);
            if (lane >= off) v += u;
        }
        wsum[lane] = v;
    }
    __syncthreads();
    int woff = (wid == 0) ? 0 : wsum[wid - 1];
    if (i < NNODES) {
        g_rowstart[i] = g_blockoff[blockIdx.x] + woff + incl - d;
        g_dinv[i] = rsqrtf((float)d + 1.0f);   // +1 = self loop
    }
    if (i == 0) g_rowstart[NNODES] = NEDGES;
}

// K4: fill CSR with (col, dinv[col]); 4 edges/thread
__global__ void k_fill(const int* __restrict__ ei) {
    int i = blockIdx.x * blockDim.x + threadIdx.x;
    if (i >= NEDGES / 4) return;
    int4 rv = ((const int4*)ei)[i];
    int4 cv = ((const int4*)(ei + NEDGES))[i];
    #pragma unroll
    for (int j = 0; j < 4; j++) {
        int r = clampi(j == 0 ? rv.x : j == 1 ? rv.y : j == 2 ? rv.z : rv.w);
        int c = clampi(j == 0 ? cv.x : j == 1 ? cv.y : j == 2 ? cv.z : cv.w);
        int slot = g_rowstart[r] + atomicAdd(&g_cursor[r], 1);
        g_cw[slot] = make_int2(c, __float_as_int(g_dinv[c]));
    }
}

// K5: h = x @ W1 with W1 column in registers; 256 thr, 32 nodes/block.
__global__ void __launch_bounds__(256) k_gemm1(const float* __restrict__ x,
                                               const float* __restrict__ W1) {
    __shared__ float4 xs[32][16];   // 32 node rows
    const int tid = threadIdx.x;
    const int g = tid >> 6;         // node sub-group 0..3
    const int t = tid & 63;         // output column
    float Wc[64];
    #pragma unroll
    for (int k = 0; k < 64; k++) Wc[k] = W1[k * 64 + t];
    const int base = blockIdx.x * 32;
    const float4* x4 = (const float4*)(x + (size_t)base * FDIM);
    for (int i = tid; i < 32 * 16; i += 256) ((float4*)xs)[i] = x4[i];
    __syncthreads();
    #pragma unroll 1
    for (int jj = 0; jj < 8; jj++) {
        const int j = g * 8 + jj;
        float acc = 0.0f;
        #pragma unroll
        for (int k4 = 0; k4 < 16; k4++) {
            float4 xv = xs[j][k4];
            acc = fmaf(xv.x, Wc[k4 * 4],     acc);
            acc = fmaf(xv.y, Wc[k4 * 4 + 1], acc);
            acc = fmaf(xv.z, Wc[k4 * 4 + 2], acc);
            acc = fmaf(xv.w, Wc[k4 * 4 + 3], acc);
        }
        g_h[(size_t)(base + j) * FDIM + t] = acc;
    }
}

// K6: fused layer-1 gather + bias + ReLU + GEMM2 -> g_h2.
// Block of 64 threads per node; unroll 8 for deep MLP on row gathers.
__global__ void k_fused1(const float* __restrict__ b1, const float* __restrict__ W2) {
    const int n = blockIdx.x;
    const int t = threadIdx.x;
    __shared__ float s0[2], s1[2];

    const float din = g_dinv[n];
    const int start = g_rowstart[n];
    const int end   = g_rowstart[n + 1];

    float acc = (din * din) * g_h[n * FDIM + t];   // self loop
    int s = start;
    for (; s + 8 <= end; s += 8) {
        int2 cw0 = g_cw[s],     cw1 = g_cw[s + 1], cw2 = g_cw[s + 2], cw3 = g_cw[s + 3];
        int2 cw4 = g_cw[s + 4], cw5 = g_cw[s + 5], cw6 = g_cw[s + 6], cw7 = g_cw[s + 7];
        float h0 = g_h[cw0.x * FDIM + t];
        float h1 = g_h[cw1.x * FDIM + t];
        float h2 = g_h[cw2.x * FDIM + t];
        float h3 = g_h[cw3.x * FDIM + t];
        float h4 = g_h[cw4.x * FDIM + t];
        float h5 = g_h[cw5.x * FDIM + t];
        float h6 = g_h[cw6.x * FDIM + t];
        float h7 = g_h[cw7.x * FDIM + t];
        acc = fmaf(din * __int_as_float(cw0.y), h0, acc);
        acc = fmaf(din * __int_as_float(cw1.y), h1, acc);
        acc = fmaf(din * __int_as_float(cw2.y), h2, acc);
        acc = fmaf(din * __int_as_float(cw3.y), h3, acc);
        acc = fmaf(din * __int_as_float(cw4.y), h4, acc);
        acc = fmaf(din * __int_as_float(cw5.y), h5, acc);
        acc = fmaf(din * __int_as_float(cw6.y), h6, acc);
        acc = fmaf(din * __int_as_float(cw7.y), h7, acc);
    }
    for (; s < end; s++) {
        int2 cw = g_cw[s];
        acc = fmaf(din * __int_as_float(cw.y), g_h[cw.x * FDIM + t], acc);
    }
    float v = fmaxf(acc + b1[t], 0.0f);

    // GEMM2: logits[n] = v @ W2 (64x2)
    float c0 = v * W2[t * 2];
    float c1 = v * W2[t * 2 + 1];
    #pragma unroll
    for (int off = 16; off > 0; off >>= 1) {
        c0 += __shfl_down_sync(0xFFFFFFFFu, c0, off);
        c1 += __shfl_down_sync(0xFFFFFFFFu, c1, off);
    }
    const int warp = t >> 5;
    if ((t & 31) == 0) { s0[warp] = c0; s1[warp] = c1; }
    __syncthreads();
    if (t == 0) {
        g_h2[n * 2]     = s0[0] + s0[1];
        g_h2[n * 2 + 1] = s1[0] + s1[1];
    }
}

// K7: fused layer-2 gather + bias + softmax -> out.  Warp per node.
__global__ void k_fused2(const float* __restrict__ b2, float* __restrict__ out) {
    const int lane = threadIdx.x & 31;
    const int n = (blockIdx.x * blockDim.x + threadIdx.x) >> 5;
    if (n >= NNODES) return;
    const float din = g_dinv[n];
    const int start = g_rowstart[n];
    const int end   = g_rowstart[n + 1];
    float a0 = 0.0f, a1 = 0.0f;
    for (int s = start + lane; s < end; s += 32) {
        int2 cw = g_cw[s];
        float w = din * __int_as_float(cw.y);
        a0 = fmaf(w, g_h2[cw.x * 2],     a0);
        a1 = fmaf(w, g_h2[cw.x * 2 + 1], a1);
    }
    #pragma unroll
    for (int off = 16; off > 0; off >>= 1) {
        a0 += __shfl_down_sync(0xFFFFFFFFu, a0, off);
        a1 += __shfl_down_sync(0xFFFFFFFFu, a1, off);
    }
    if (lane == 0) {
        float sl = din * din;
        float l0 = b2[0] + fmaf(sl, g_h2[n * 2],     a0);
        float l1 = b2[1] + fmaf(sl, g_h2[n * 2 + 1], a1);
        float m = fmaxf(l0, l1);
        float e0 = __expf(l0 - m), e1 = __expf(l1 - m);
        float inv = 1.0f / (e0 + e1);
        out[n * 2]     = e0 * inv;
        out[n * 2 + 1] = e1 * inv;
    }
}

extern "C" void kernel_launch(void* const* d_in, const int* in_sizes, int n_in,
                              void* d_out, int out_size) {
    const float* x  = (const float*)d_in[0];
    const int*   ei = (const int*)d_in[1];     // int32 (JAX x64 disabled)
    const float* W1 = (const float*)d_in[2];
    const float* b1 = (const float*)d_in[3];
    const float* W2 = (const float*)d_in[4];
    const float* b2 = (const float*)d_in[5];
    float* out = (float*)d_out;

    const int T = 256;
    k_zero   <<<(NNODES + T - 1) / T, T>>>();
    k_degree <<<(NEDGES / 4 + T - 1) / T, T>>>(ei);
    k_scan_a <<<NB, 256>>>();
    k_scan_b <<<1, 128>>>();
    k_scan_c <<<NB, 1024>>>();
    k_fill   <<<(NEDGES / 4 + T - 1) / T, T>>>(ei);
    k_gemm1  <<<NNODES / 32, 256>>>(x, W1);
    k_fused1 <<<NNODES, FDIM>>>(b1, W2);
    k_fused2 <<<(NNODES * 32 + T - 1) / T, T>>>(b2, out);
}

// round 7
// speedup vs baseline: 2.4235x; 1.1230x over previous
#include <cuda_runtime.h>
#include <cuda_bf16.h>
#include <cuda_fp16.h>
#include <stdint.h>

#define NNODES 100000
#define NEDGES 1600000
#define FDIM   64
#define NCLS   2
#define NB     98            // ceil(NNODES/1024)

// Scratch (__device__ globals; no allocations allowed)
__device__ int   g_deg[NNODES];
__device__ int   g_cursor[NNODES];
__device__ int   g_rowstart[NNODES + 1];
__device__ int2  g_cw[NEDGES];                 // CSR slot: {col, bits(dinv[col])}
__device__ float g_dinv[NNODES];
__device__ __align__(16) __half2 g_hh[NNODES * 32];   // x @ W1, fp16 pairs
__device__ float g_h2[NNODES * NCLS];          // relu(agg1 + b1) @ W2
__device__ int   g_partial[NB];
__device__ int   g_blockoff[NB];

__device__ __forceinline__ int clampi(int v) {
    return min(max(v, 0), NNODES - 1);
}

// ---------------------------------------------------------------------------
// K1: zero degree + cursor
__global__ void k_zero(void) {
    int i = blockIdx.x * blockDim.x + threadIdx.x;
    if (i < NNODES) { g_deg[i] = 0; g_cursor[i] = 0; }
}

// K2: degree histogram over edge targets, 4 edges/thread via int4
__global__ void k_degree(const int* __restrict__ ei) {
    int i = blockIdx.x * blockDim.x + threadIdx.x;
    if (i >= NEDGES / 4) return;
    int4 v = ((const int4*)ei)[i];
    atomicAdd(&g_deg[clampi(v.x)], 1);
    atomicAdd(&g_deg[clampi(v.y)], 1);
    atomicAdd(&g_deg[clampi(v.z)], 1);
    atomicAdd(&g_deg[clampi(v.w)], 1);
}

// K3a: per-1024-chunk partial sums
__global__ void k_scan_a(void) {
    __shared__ int ws[8];
    const int t = threadIdx.x;
    const int base = blockIdx.x * 1024;
    int sum = 0;
    #pragma unroll
    for (int i = 0; i < 4; i++) {
        int idx = base + t + i * 256;
        if (idx < NNODES) sum += g_deg[idx];
    }
    #pragma unroll
    for (int off = 16; off > 0; off >>= 1) sum += __shfl_down_sync(~0u, sum, off);
    if ((t & 31) == 0) ws[t >> 5] = sum;
    __syncthreads();
    if (t == 0) {
        int s = 0;
        #pragma unroll
        for (int w = 0; w < 8; w++) s += ws[w];
        g_partial[blockIdx.x] = s;
    }
}

// K3b: scan the 98 partials (one block)
__global__ void k_scan_b(void) {
    __shared__ int sp[128];
    const int t = threadIdx.x;
    int v = (t < NB) ? g_partial[t] : 0;
    sp[t] = v;
    __syncthreads();
    for (int off = 1; off < 128; off <<= 1) {
        int u = (t >= off) ? sp[t - off] : 0;
        __syncthreads();
        sp[t] += u;
        __syncthreads();
    }
    if (t < NB) g_blockoff[t] = sp[t] - v;   // exclusive
}

// K3c: intra-chunk exclusive scan + write rowstart & dinv
__global__ void k_scan_c(void) {
    __shared__ int wsum[32];
    const int t = threadIdx.x;
    const int lane = t & 31, wid = t >> 5;
    const int i = blockIdx.x * 1024 + t;
    int d = (i < NNODES) ? g_deg[i] : 0;
    int incl = d;
    #pragma unroll
    for (int off = 1; off < 32; off <<= 1) {
        int v = __shfl_up_sync(~0u, incl, off);
        if (lane >= off) incl += v;
    }
    if (lane == 31) wsum[wid] = incl;
    __syncthreads();
    if (wid == 0) {
        int v = wsum[lane];
        #pragma unroll
        for (int off = 1; off < 32; off <<= 1) {
            int u = __shfl_up_sync(~0u, v, off);
            if (lane >= off) v += u;
        }
        wsum[lane] = v;
    }
    __syncthreads();
    int woff = (wid == 0) ? 0 : wsum[wid - 1];
    if (i < NNODES) {
        g_rowstart[i] = g_blockoff[blockIdx.x] + woff + incl - d;
        g_dinv[i] = rsqrtf((float)d + 1.0f);   // +1 = self loop
    }
    if (i == 0) g_rowstart[NNODES] = NEDGES;
}

// K4: fill CSR with (col, dinv[col]); 4 edges/thread
__global__ void k_fill(const int* __restrict__ ei) {
    int i = blockIdx.x * blockDim.x + threadIdx.x;
    if (i >= NEDGES / 4) return;
    int4 rv = ((const int4*)ei)[i];
    int4 cv = ((const int4*)(ei + NEDGES))[i];
    #pragma unroll
    for (int j = 0; j < 4; j++) {
        int r = clampi(j == 0 ? rv.x : j == 1 ? rv.y : j == 2 ? rv.z : rv.w);
        int c = clampi(j == 0 ? cv.x : j == 1 ? cv.y : j == 2 ? cv.z : cv.w);
        int slot = g_rowstart[r] + atomicAdd(&g_cursor[r], 1);
        g_cw[slot] = make_int2(c, __float_as_int(g_dinv[c]));
    }
}

// K5: h = x @ W1 via packed f32x2 FMA; thread owns output column t.
// 256 thr, 32 nodes/block; write fp16 half2 rows.
__global__ void __launch_bounds__(256) k_gemm1(const float* __restrict__ x,
                                               const float* __restrict__ W1) {
    __shared__ float4 xs[32][16];   // 32 node rows
    const int tid = threadIdx.x;
    const int g = tid >> 6;         // node sub-group 0..3
    const int t = tid & 63;         // output column
    unsigned long long Wc2[32];     // W1[:,t] packed by k-pairs
    #pragma unroll
    for (int k2 = 0; k2 < 32; k2++) {
        float w0 = W1[(2 * k2) * 64 + t];
        float w1 = W1[(2 * k2 + 1) * 64 + t];
        asm("mov.b64 %0,{%1,%2};" : "=l"(Wc2[k2]) : "f"(w0), "f"(w1));
    }
    const int base = blockIdx.x * 32;
    const float4* x4 = (const float4*)(x + (size_t)base * FDIM);
    for (int i = tid; i < 32 * 16; i += 256) ((float4*)xs)[i] = x4[i];
    __syncthreads();
    #pragma unroll 1
    for (int jj = 0; jj < 8; jj++) {
        const int j = g * 8 + jj;
        unsigned long long accA = 0, accB = 0;
        #pragma unroll
        for (int k4 = 0; k4 < 16; k4++) {
            float4 xv = xs[j][k4];
            unsigned long long a01, a23;
            asm("mov.b64 %0,{%1,%2};" : "=l"(a01) : "f"(xv.x), "f"(xv.y));
            asm("mov.b64 %0,{%1,%2};" : "=l"(a23) : "f"(xv.z), "f"(xv.w));
            asm("fma.rn.f32x2 %0,%1,%2,%0;" : "+l"(accA) : "l"(a01), "l"(Wc2[2 * k4]));
            asm("fma.rn.f32x2 %0,%1,%2,%0;" : "+l"(accB) : "l"(a23), "l"(Wc2[2 * k4 + 1]));
        }
        float lo0, hi0, lo1, hi1;
        asm("mov.b64 {%0,%1},%2;" : "=f"(lo0), "=f"(hi0) : "l"(accA));
        asm("mov.b64 {%0,%1},%2;" : "=f"(lo1), "=f"(hi1) : "l"(accB));
        float acc = (lo0 + lo1) + (hi0 + hi1);
        float nb = __shfl_down_sync(~0u, acc, 1);   // col t+1 (same warp)
        if ((t & 1) == 0)
            g_hh[(size_t)(base + j) * 32 + (t >> 1)] = __floats2half2_rn(acc, nb);
    }
}

// K6: fused layer-1 gather + bias + ReLU + GEMM2 -> g_h2.
// Warp per node (lane owns half2 = features 2l,2l+1); unroll 8 for MLP.
__global__ void __launch_bounds__(256) k_fused1(const float* __restrict__ b1,
                                                const float* __restrict__ W2) {
    const int warp = threadIdx.x >> 5;
    const int l = threadIdx.x & 31;
    const int n = blockIdx.x * 8 + warp;
    if (n >= NNODES) return;

    const float din = g_dinv[n];
    const int start = g_rowstart[n];
    const int end   = g_rowstart[n + 1];

    float2 sv = __half22float2(g_hh[(size_t)n * 32 + l]);
    const float sl = din * din;
    float a0 = sl * sv.x, a1 = sl * sv.y;     // self loop

    int s = start;
    for (; s + 8 <= end; s += 8) {
        int2 cw0 = g_cw[s],     cw1 = g_cw[s + 1], cw2 = g_cw[s + 2], cw3 = g_cw[s + 3];
        int2 cw4 = g_cw[s + 4], cw5 = g_cw[s + 5], cw6 = g_cw[s + 6], cw7 = g_cw[s + 7];
        __half2 h0 = g_hh[(size_t)cw0.x * 32 + l];
        __half2 h1 = g_hh[(size_t)cw1.x * 32 + l];
        __half2 h2 = g_hh[(size_t)cw2.x * 32 + l];
        __half2 h3 = g_hh[(size_t)cw3.x * 32 + l];
        __half2 h4 = g_hh[(size_t)cw4.x * 32 + l];
        __half2 h5 = g_hh[(size_t)cw5.x * 32 + l];
        __half2 h6 = g_hh[(size_t)cw6.x * 32 + l];
        __half2 h7 = g_hh[(size_t)cw7.x * 32 + l];
        float w0 = din * __int_as_float(cw0.y);
        float w1 = din * __int_as_float(cw1.y);
        float w2 = din * __int_as_float(cw2.y);
        float w3 = din * __int_as_float(cw3.y);
        float w4 = din * __int_as_float(cw4.y);
        float w5 = din * __int_as_float(cw5.y);
        float w6 = din * __int_as_float(cw6.y);
        float w7 = din * __int_as_float(cw7.y);
        float2 f;
        f = __half22float2(h0); a0 = fmaf(w0, f.x, a0); a1 = fmaf(w0, f.y, a1);
        f = __half22float2(h1); a0 = fmaf(w1, f.x, a0); a1 = fmaf(w1, f.y, a1);
        f = __half22float2(h2); a0 = fmaf(w2, f.x, a0); a1 = fmaf(w2, f.y, a1);
        f = __half22float2(h3); a0 = fmaf(w3, f.x, a0); a1 = fmaf(w3, f.y, a1);
        f = __half22float2(h4); a0 = fmaf(w4, f.x, a0); a1 = fmaf(w4, f.y, a1);
        f = __half22float2(h5); a0 = fmaf(w5, f.x, a0); a1 = fmaf(w5, f.y, a1);
        f = __half22float2(h6); a0 = fmaf(w6, f.x, a0); a1 = fmaf(w6, f.y, a1);
        f = __half22float2(h7); a0 = fmaf(w7, f.x, a0); a1 = fmaf(w7, f.y, a1);
    }
    for (; s < end; s++) {
        int2 cw = g_cw[s];
        float w = din * __int_as_float(cw.y);
        float2 f = __half22float2(g_hh[(size_t)cw.x * 32 + l]);
        a0 = fmaf(w, f.x, a0);
        a1 = fmaf(w, f.y, a1);
    }

    float v0 = fmaxf(a0 + b1[2 * l],     0.0f);
    float v1 = fmaxf(a1 + b1[2 * l + 1], 0.0f);

    // GEMM2: logits[n] = v @ W2 (64x2)
    float c0 = fmaf(v0, W2[(2 * l) * 2],     v1 * W2[(2 * l + 1) * 2]);
    float c1 = fmaf(v0, W2[(2 * l) * 2 + 1], v1 * W2[(2 * l + 1) * 2 + 1]);
    #pragma unroll
    for (int off = 16; off > 0; off >>= 1) {
        c0 += __shfl_down_sync(0xFFFFFFFFu, c0, off);
        c1 += __shfl_down_sync(0xFFFFFFFFu, c1, off);
    }
    if (l == 0) {
        g_h2[n * 2]     = c0;
        g_h2[n * 2 + 1] = c1;
    }
}

// K7: fused layer-2 gather + bias + softmax -> out.  Warp per node.
__global__ void k_fused2(const float* __restrict__ b2, float* __restrict__ out) {
    const int lane = threadIdx.x & 31;
    const int n = (blockIdx.x * blockDim.x + threadIdx.x) >> 5;
    if (n >= NNODES) return;
    const float din = g_dinv[n];
    const int start = g_rowstart[n];
    const int end   = g_rowstart[n + 1];
    float a0 = 0.0f, a1 = 0.0f;
    for (int s = start + lane; s < end; s += 32) {
        int2 cw = g_cw[s];
        float w = din * __int_as_float(cw.y);
        a0 = fmaf(w, g_h2[cw.x * 2],     a0);
        a1 = fmaf(w, g_h2[cw.x * 2 + 1], a1);
    }
    #pragma unroll
    for (int off = 16; off > 0; off >>= 1) {
        a0 += __shfl_down_sync(0xFFFFFFFFu, a0, off);
        a1 += __shfl_down_sync(0xFFFFFFFFu, a1, off);
    }
    if (lane == 0) {
        float sl = din * din;
        float l0 = b2[0] + fmaf(sl, g_h2[n * 2],     a0);
        float l1 = b2[1] + fmaf(sl, g_h2[n * 2 + 1], a1);
        float m = fmaxf(l0, l1);
        float e0 = __expf(l0 - m), e1 = __expf(l1 - m);
        float inv = 1.0f / (e0 + e1);
        out[n * 2]     = e0 * inv;
        out[n * 2 + 1] = e1 * inv;
    }
}

extern "C" void kernel_launch(void* const* d_in, const int* in_sizes, int n_in,
                              void* d_out, int out_size) {
    const float* x  = (const float*)d_in[0];
    const int*   ei = (const int*)d_in[1];     // int32 (JAX x64 disabled)
    const float* W1 = (const float*)d_in[2];
    const float* b1 = (const float*)d_in[3];
    const float* W2 = (const float*)d_in[4];
    const float* b2 = (const float*)d_in[5];
    float* out = (float*)d_out;

    const int T = 256;
    k_zero   <<<(NNODES + T - 1) / T, T>>>();
    k_degree <<<(NEDGES / 4 + T - 1) / T, T>>>(ei);
    k_scan_a <<<NB, 256>>>();
    k_scan_b <<<1, 128>>>();
    k_scan_c <<<NB, 1024>>>();
    k_fill   <<<(NEDGES / 4 + T - 1) / T, T>>>(ei);
    k_gemm1  <<<NNODES / 32, 256>>>(x, W1);
    k_fused1 <<<(NNODES + 7) / 8, 256>>>(b1, W2);
    k_fused2 <<<(NNODES * 32 + T - 1) / T, T>>>(b2, out);
}